// round 14
// baseline (speedup 1.0000x reference)
#include <cuda_runtime.h>
#include <cuda_bf16.h>
#include <stdint.h>

#define THREADS 256
#define ITEMS   8
#define CHUNK   (THREADS * ITEMS)   // 2048
#define NWARPS  (THREADS / 32)      // 8
#define HALFC   25                  // chunks in first half-row
#define MAXB    4096

__device__ int   g_K[MAXB];
__device__ float g_Fx[MAXB], g_Fy[MAXB], g_Fz[MAXB];

// ---------------- shared helpers ----------------
static __device__ __forceinline__ void ldst8(const int* __restrict__ srow, int T,
                                             int c, int tid, int4& A, int4& B) {
    const int t0 = c * CHUNK + tid * ITEMS;
    if (t0 + ITEMS <= T) {
        A = *reinterpret_cast<const int4*>(srow + t0);
        B = *reinterpret_cast<const int4*>(srow + t0 + 4);
    } else {
        int s[8] = {1,1,1,1,1,1,1,1};
        #pragma unroll
        for (int i = 0; i < ITEMS; i++)
            if (t0 + i < T) s[i] = srow[t0 + i];
        A = make_int4(s[0], s[1], s[2], s[3]);
        B = make_int4(s[4], s[5], s[6], s[7]);
    }
}

static __device__ __forceinline__ unsigned mkmask(int4 A, int4 B, int c, int tid, int T) {
    const int t0 = c * CHUNK + tid * ITEMS;
    const int s[8] = {A.x, A.y, A.z, A.w, B.x, B.y, B.z, B.w};
    unsigned tb = 0, s0 = 0, zm = 0;
    #pragma unroll
    for (int i = 0; i < ITEMS; i++) {
        const unsigned isT = (s[i] == 2);
        const unsigned inv = (t0 + i >= T);
        tb |= isT << i;
        s0 |= (unsigned)(s[i] == 0) << i;
        zm |= (isT | inv) << i;
    }
    return tb | (s0 << 8) | (zm << 16);
}

static __device__ __forceinline__ void issue24(const float* __restrict__ erow,
                                               int kb, unsigned M, float* g) {
    const unsigned tb = M & 0xffu;
    #pragma unroll
    for (int i = 0; i < ITEMS; i++) {
        const int k = kb + __popc(tb & ((2u << i) - 1u));
        const float* e = erow + (size_t)k * 3;
        g[3*i+0] = __ldg(e + 0);
        g[3*i+1] = __ldg(e + 1);
        g[3*i+2] = __ldg(e + 2);
    }
}

static __device__ __forceinline__ void consume_tot(unsigned M, const float* g,
                                                   float sp0, float sp1,
                                                   float& ax, float& ay, float& az) {
    const unsigned s0 = (M >> 8) & 0xffu, zm = (M >> 16) & 0xffu;
    ax = 0.f; ay = 0.f; az = 0.f;
    #pragma unroll
    for (int i = 0; i < ITEMS; i++) {
        const float sp = ((zm >> i) & 1u) ? 0.f : (((s0 >> i) & 1u) ? sp0 : sp1);
        ax = fmaf(g[3*i+0], sp, ax);
        ay = fmaf(g[3*i+1], sp, ay);
        az = fmaf(g[3*i+2], sp, az);
    }
}

// =============== Kernel A: first-half aggregates per row ===================
__global__ __launch_bounds__(THREADS, 2)
void kA_agg(const int*   __restrict__ states,
            const float* __restrict__ e0s,
            const float* __restrict__ speed0,
            const float* __restrict__ speed1,
            int T, int P)
{
    __shared__ int   s_i[2][NWARPS][2];
    __shared__ float s_r[NWARPS][3];

    const int b = blockIdx.x;
    const int*   srow = states + (size_t)b * T;
    const float* erow = e0s    + (size_t)b * (T + 1) * 3;
    const float sp0 = speed0[b], sp1 = speed1[b];
    const int tid = threadIdx.x, lane = tid & 31, wid = tid >> 5;

    const int HC = (HALFC < P) ? HALFC : P;

    int K = 0;
    float fx = 0.f, fy = 0.f, fz = 0.f;
    float ga[24], gb[24];
    int par = 0;

    for (int c = 0; c < HC; c += 2, par ^= 1) {
        const bool h1 = (c + 1) < HC;
        int4 A, B;
        ldst8(srow, T, c, tid, A, B);
        const unsigned m0 = mkmask(A, B, c, tid, T);
        unsigned m1 = 0x00FF0000u;
        if (h1) { ldst8(srow, T, c + 1, tid, A, B); m1 = mkmask(A, B, c + 1, tid, T); }

        const int c0 = __popc(m0 & 0xffu), c1 = __popc(m1 & 0xffu);
        int a0 = c0, a1 = c1;
        #pragma unroll
        for (int d = 1; d < 32; d <<= 1) {
            const int y0 = __shfl_up_sync(0xffffffffu, a0, d);
            const int y1 = __shfl_up_sync(0xffffffffu, a1, d);
            if (lane >= d) { a0 += y0; a1 += y1; }
        }
        if (lane == 31) { s_i[par][wid][0] = a0; s_i[par][wid][1] = a1; }
        __syncthreads();
        int w0e = 0, t0s = 0, w1e = 0, t1s = 0;
        #pragma unroll
        for (int j = 0; j < NWARPS; j++) {
            const int v0 = s_i[par][j][0], v1 = s_i[par][j][1];
            if (j < wid) { w0e += v0; w1e += v1; }
            t0s += v0; t1s += v1;
        }
        const int kb0 = K + w0e + (a0 - c0);
        const int kb1 = K + t0s + w1e + (a1 - c1);
        K += t0s + t1s;

        issue24(erow, kb0, m0, ga);
        if (h1) issue24(erow, kb1, m1, gb);
        float ax, ay, az;
        consume_tot(m0, ga, sp0, sp1, ax, ay, az);
        fx += ax; fy += ay; fz += az;
        if (h1) {
            consume_tot(m1, gb, sp0, sp1, ax, ay, az);
            fx += ax; fy += ay; fz += az;
        }
    }

    // block reduce fx,fy,fz
    #pragma unroll
    for (int d = 16; d; d >>= 1) {
        fx += __shfl_down_sync(0xffffffffu, fx, d);
        fy += __shfl_down_sync(0xffffffffu, fy, d);
        fz += __shfl_down_sync(0xffffffffu, fz, d);
    }
    if (lane == 0) { s_r[wid][0] = fx; s_r[wid][1] = fy; s_r[wid][2] = fz; }
    __syncthreads();
    if (tid == 0) {
        float tx = 0.f, ty = 0.f, tz = 0.f;
        #pragma unroll
        for (int j = 0; j < NWARPS; j++) { tx += s_r[j][0]; ty += s_r[j][1]; tz += s_r[j][2]; }
        g_K [b] = K;
        g_Fx[b] = tx; g_Fy[b] = ty; g_Fz[b] = tz;
    }
}

// =============== Kernel B: half-row serial scan (3 CTAs/SM) ================
__global__ __launch_bounds__(THREADS, 3)
void kB_scan(const int*   __restrict__ states,
             const float* __restrict__ e0s,
             const float* __restrict__ speed0,
             const float* __restrict__ speed1,
             const float* __restrict__ x0,
             float*       __restrict__ X,
             int T, int P)
{
    __shared__ float4 s_t[2][NWARPS];

    const int h = blockIdx.x;            // half index (0 or 1)
    const int b = blockIdx.y;            // row
    const int c0 = h * HALFC;
    int cN = (h == 0) ? ((HALFC < P) ? HALFC : P) : (P - HALFC);
    if (cN <= 0) return;

    const int*   srow = states + (size_t)b * T;
    const float* erow = e0s    + (size_t)b * (T + 1) * 3;
    float*       xrow = X      + (size_t)b * T * 3;
    const float sp0 = speed0[b], sp1 = speed1[b];
    const float ox = x0[3*b+0], oy = x0[3*b+1], oz = x0[3*b+2];
    const float DT = 0.1f;
    const int tid = threadIdx.x, lane = tid & 31, wid = tid >> 5;

    int   Kn = h ? g_K [b] : 0;
    float cfx = h ? g_Fx[b] : 0.f;
    float cfy = h ? g_Fy[b] : 0.f;
    float cfz = h ? g_Fz[b] : 0.f;

    float ga[24];
    unsigned m0, m1;

    // ---- prologue: kbase for chunk c0, issue, load mask of c0+1 ----
    {
        int4 A, B;
        ldst8(srow, T, c0, tid, A, B);
        m0 = mkmask(A, B, c0, tid, T);
        const int r0 = __popc(m0 & 0xffu);
        int a0 = r0;
        #pragma unroll
        for (int d = 1; d < 32; d <<= 1) {
            const int y = __shfl_up_sync(0xffffffffu, a0, d);
            if (lane >= d) a0 += y;
        }
        if (lane == 31) s_t[0][wid] = make_float4((float)a0, 0.f, 0.f, 0.f);
        __syncthreads();
        int w0e = 0, tot0 = 0;
        #pragma unroll
        for (int j = 0; j < NWARPS; j++) {
            const int v = (int)s_t[0][j].x;
            if (j < wid) w0e += v;
            tot0 += v;
        }
        issue24(erow, Kn + w0e + (a0 - r0), m0, ga);
        Kn += tot0;
        if (cN > 1) { ldst8(srow, T, c0 + 1, tid, A, B); m1 = mkmask(A, B, c0 + 1, tid, T); }
        else m1 = 0x00FF0000u;
        __syncthreads();       // protect s_t[0] before body 0
    }

    int par = 0;
    for (int i = 0; i < cN; i++, par ^= 1) {
        // prefetch states for chunk c0+i+2 -> next m1
        int4 na, nb;
        const bool hs = (i + 2) < cN;
        if (hs) ldst8(srow, T, c0 + i + 2, tid, na, nb);

        // consume current chunk -> totals
        float ax, ay, az;
        consume_tot(m0, ga, sp0, sp1, ax, ay, az);

        // fused 4-comp scan: (ax, ay, az, run of chunk i+1)
        const int rn = __popc(m1 & 0xffu);
        float sx = ax, sy = ay, sz = az, sr = (float)rn;
        #pragma unroll
        for (int d = 1; d < 32; d <<= 1) {
            const float tx = __shfl_up_sync(0xffffffffu, sx, d);
            const float ty = __shfl_up_sync(0xffffffffu, sy, d);
            const float tz = __shfl_up_sync(0xffffffffu, sz, d);
            const float tr = __shfl_up_sync(0xffffffffu, sr, d);
            if (lane >= d) { sx += tx; sy += ty; sz += tz; sr += tr; }
        }
        if (lane == 31) s_t[par][wid] = make_float4(sx, sy, sz, sr);
        __syncthreads();
        float wxe = 0.f, wye = 0.f, wze = 0.f, wre = 0.f;
        float txs = 0.f, tys = 0.f, tzs = 0.f, trs = 0.f;
        #pragma unroll
        for (int j = 0; j < NWARPS; j++) {
            const float4 t = s_t[par][j];
            if (j < wid) { wxe += t.x; wye += t.y; wze += t.z; wre += t.w; }
            txs += t.x; tys += t.y; tzs += t.z; trs += t.w;
        }
        const float ex = cfx + wxe + (sx - ax);
        const float ey = cfy + wye + (sy - ay);
        const float ez = cfz + wze + (sz - az);
        const int kbn = Kn + (int)wre + (int)(sr - (float)rn);
        cfx += txs; cfy += tys; cfz += tzs;
        Kn  += (int)trs;

        // store chunk c0+i: recompute running prefix from ga + m0
        {
            const int t0 = (c0 + i) * CHUNK + tid * ITEMS;
            const unsigned s0m = (m0 >> 8) & 0xffu, zm = (m0 >> 16) & 0xffu;
            float rx = ex, ry = ey, rz = ez;
            if (t0 + ITEMS <= T) {
                float4* q = reinterpret_cast<float4*>(xrow + (size_t)t0 * 3);
                float o[24];
                #pragma unroll
                for (int ii = 0; ii < ITEMS; ii++) {
                    const float sp = ((zm >> ii) & 1u) ? 0.f
                                   : (((s0m >> ii) & 1u) ? sp0 : sp1);
                    rx = fmaf(ga[3*ii+0], sp, rx);
                    ry = fmaf(ga[3*ii+1], sp, ry);
                    rz = fmaf(ga[3*ii+2], sp, rz);
                    o[3*ii+0] = fmaf(DT, rx, ox);
                    o[3*ii+1] = fmaf(DT, ry, oy);
                    o[3*ii+2] = fmaf(DT, rz, oz);
                }
                #pragma unroll
                for (int g2 = 0; g2 < 6; g2++)
                    __stwt(q + g2, make_float4(o[4*g2+0], o[4*g2+1],
                                               o[4*g2+2], o[4*g2+3]));
            } else {
                #pragma unroll
                for (int ii = 0; ii < ITEMS; ii++) {
                    const float sp = ((zm >> ii) & 1u) ? 0.f
                                   : (((s0m >> ii) & 1u) ? sp0 : sp1);
                    rx = fmaf(ga[3*ii+0], sp, rx);
                    ry = fmaf(ga[3*ii+1], sp, ry);
                    rz = fmaf(ga[3*ii+2], sp, rz);
                    if (t0 + ii < T) {
                        float* p = xrow + (size_t)(t0 + ii) * 3;
                        p[0] = fmaf(DT, rx, ox);
                        p[1] = fmaf(DT, ry, oy);
                        p[2] = fmaf(DT, rz, oz);
                    }
                }
            }
        }

        // refill ga for chunk c0+i+1
        if (i + 1 < cN) issue24(erow, kbn, m1, ga);

        m0 = m1;
        m1 = hs ? mkmask(na, nb, c0 + i + 2, tid, T) : 0x00FF0000u;
    }
}

extern "C" void kernel_launch(void* const* d_in, const int* in_sizes, int n_in,
                              void* d_out, int out_size)
{
    const int*   states = (const int*)  d_in[0];
    const float* e0s    = (const float*)d_in[1];
    const float* sp0    = (const float*)d_in[2];
    const float* sp1    = (const float*)d_in[3];
    const float* x0     = (const float*)d_in[4];
    float*       X      = (float*)d_out;

    const int B = in_sizes[2];            // speed_0 has B elements
    const int T = in_sizes[0] / B;        // states is (B, T)
    const int P = (T + CHUNK - 1) / CHUNK;

    kA_agg<<<B, THREADS>>>(states, e0s, sp0, sp1, T, P);
    dim3 gridB(2, B);
    kB_scan<<<gridB, THREADS>>>(states, e0s, sp0, sp1, x0, X, T, P);
}